// round 8
// baseline (speedup 1.0000x reference)
#include <cuda_runtime.h>
#include <cuda_fp16.h>
#include <cstdint>

#define NN_D 256          // feature dim D
#define KNEI 16           // neighbors per node

// 50000 * 256 floats = 51.2 MB scratch for the GEMM output ("support")
__device__ float g_support[50000 * 256];

// ---------------------------------------------------------------------------
// GEMM via mma.sync fp16 (single MMA per fragment; fp16 rounding error on both
// operands ~2^-11, final rel_err ~5e-4 < 1e-3 gate thanks to fp32 accumulate
// and tanh saturation downstream).
// C[M,256] = A[M,256] @ W[256,256]^T + b_lin
// CTA tile 128x128, 8 warps (4M x 2N), warp tile 32x64, K-chunk 64.
// ---------------------------------------------------------------------------
#define BM 128
#define BN 128
#define KC 64
#define LDS 72            // padded fp16 leading dim (conflict-free ldmatrix)

#define AS   0
#define BS   (BM * LDS * 2)           // 18432
#define SMEM_GEMM (2 * BM * LDS * 2)  // 36864

__device__ __forceinline__ uint32_t smem_u32(const void* p) {
    uint32_t a;
    asm("{ .reg .u64 t; cvta.to.shared.u64 t, %1; cvt.u32.u64 %0, t; }"
        : "=r"(a) : "l"(p));
    return a;
}

__device__ __forceinline__ uint32_t cvt_f16x2(float x, float y) {
    __half2 hh;
    hh.x = __float2half_rn(x);
    hh.y = __float2half_rn(y);
    return *reinterpret_cast<uint32_t*>(&hh);
}

__device__ __forceinline__ void ldm_x4(uint32_t& r0, uint32_t& r1, uint32_t& r2,
                                       uint32_t& r3, uint32_t addr) {
    asm volatile("ldmatrix.sync.aligned.m8n8.x4.shared.b16 {%0,%1,%2,%3}, [%4];"
                 : "=r"(r0), "=r"(r1), "=r"(r2), "=r"(r3) : "r"(addr));
}

__device__ __forceinline__ void mma16816(float* c, const uint32_t* a, const uint32_t* b) {
    asm volatile(
        "mma.sync.aligned.m16n8k16.row.col.f32.f16.f16.f32 "
        "{%0,%1,%2,%3}, {%4,%5,%6,%7}, {%8,%9}, {%0,%1,%2,%3};"
        : "+f"(c[0]), "+f"(c[1]), "+f"(c[2]), "+f"(c[3])
        : "r"(a[0]), "r"(a[1]), "r"(a[2]), "r"(a[3]), "r"(b[0]), "r"(b[1]));
}

__global__ __launch_bounds__(256) void gemm_mma_kernel(
    const float* __restrict__ A,
    const float* __restrict__ W,
    const float* __restrict__ blin,
    float* __restrict__ C,
    int M)
{
    extern __shared__ char smem[];
    const uint32_t sbase = smem_u32(smem);
    const int tid  = threadIdx.x;
    const int wid  = tid >> 5;
    const int lane = tid & 31;
    const int warp_m = wid & 3;       // 0..3 -> 32-row slice
    const int warp_n = wid >> 2;      // 0..1 -> 64-col slice
    const int bm = blockIdx.x * BM;
    const int bn = blockIdx.y * BN;

    float acc[2][8][4];
#pragma unroll
    for (int i = 0; i < 2; i++)
#pragma unroll
        for (int j = 0; j < 8; j++)
#pragma unroll
            for (int v = 0; v < 4; v++) acc[i][j][v] = 0.0f;

    // ldmatrix source addresses (per-lane)
    const int a_row = warp_m * 32 + (lane & 15);
    const int a_col = (lane >> 4) * 8;
    const uint32_t a_base = sbase + AS + (uint32_t)(a_row * LDS + a_col) * 2;
    const int b_row_base = warp_n * 64 + ((lane >> 4) << 3) + (lane & 7);
    const int b_col = ((lane >> 3) & 1) * 8;
    const uint32_t b_base = sbase + BS + (uint32_t)(b_row_base * LDS + b_col) * 2;

    for (int c = 0; c < NN_D / KC; c++) {        // 4 K-chunks
        // ---- global -> smem (convert fp32 -> fp16) ----
        // full tile: 128 rows x 64 k = 2048 float4 loads (8 per thread each op)
#pragma unroll
        for (int i = tid; i < BM * (KC / 4); i += 256) {
            const int row = i >> 4;              // 0..127
            const int q   = i & 15;              // 0..15 -> k offset q*4
            const int gr  = bm + row;
            float4 v = (gr < M)
                ? *reinterpret_cast<const float4*>(A + (size_t)gr * NN_D + c * KC + q * 4)
                : make_float4(0.f, 0.f, 0.f, 0.f);
            const uint32_t off = (uint32_t)(row * LDS + q * 4) * 2;
            *reinterpret_cast<uint2*>(smem + AS + off) =
                make_uint2(cvt_f16x2(v.x, v.y), cvt_f16x2(v.z, v.w));

            float4 w = *reinterpret_cast<const float4*>(
                W + (size_t)(bn + row) * NN_D + c * KC + q * 4);
            *reinterpret_cast<uint2*>(smem + BS + off) =
                make_uint2(cvt_f16x2(w.x, w.y), cvt_f16x2(w.z, w.w));
        }
        __syncthreads();

        // ---- compute: 4 k-steps of 16 ----
#pragma unroll
        for (int ks = 0; ks < KC / 16; ks++) {
            const uint32_t koff = (uint32_t)(ks * 16) * 2;

            uint32_t af[2][4];
            ldm_x4(af[0][0], af[0][1], af[0][2], af[0][3], a_base + koff);
            ldm_x4(af[1][0], af[1][1], af[1][2], af[1][3], a_base + koff + 16 * LDS * 2);

            uint32_t bf[8][2];
#pragma unroll
            for (int np = 0; np < 4; np++) {
                const uint32_t bo = b_base + koff + (uint32_t)(np * 16 * LDS) * 2;
                ldm_x4(bf[2 * np][0], bf[2 * np][1], bf[2 * np + 1][0], bf[2 * np + 1][1], bo);
            }

#pragma unroll
            for (int mi = 0; mi < 2; mi++) {
#pragma unroll
                for (int nj = 0; nj < 8; nj++) {
                    mma16816(acc[mi][nj], af[mi], bf[nj]);
                }
            }
        }
        __syncthreads();
    }

    // ---- epilogue: + b_lin, store ----
    float2 blv[8];
#pragma unroll
    for (int nj = 0; nj < 8; nj++) {
        const int col = bn + warp_n * 64 + nj * 8 + (lane & 3) * 2;
        blv[nj].x = __ldg(blin + col);
        blv[nj].y = __ldg(blin + col + 1);
    }
#pragma unroll
    for (int mi = 0; mi < 2; mi++) {
        const int r0 = bm + warp_m * 32 + mi * 16 + (lane >> 2);
        const int r1 = r0 + 8;
#pragma unroll
        for (int nj = 0; nj < 8; nj++) {
            const int col = bn + warp_n * 64 + nj * 8 + (lane & 3) * 2;
            if (r0 < M) {
                float2 o = make_float2(acc[mi][nj][0] + blv[nj].x,
                                       acc[mi][nj][1] + blv[nj].y);
                *reinterpret_cast<float2*>(C + (size_t)r0 * NN_D + col) = o;
            }
            if (r1 < M) {
                float2 o = make_float2(acc[mi][nj][2] + blv[nj].x,
                                       acc[mi][nj][3] + blv[nj].y);
                *reinterpret_cast<float2*>(C + (size_t)r1 * NN_D + col) = o;
            }
        }
    }
}

// ---------------------------------------------------------------------------
// Aggregation: out[n][d] = tanh(sum_k sup[a2a[n][k]][d] * fe[n2e[n][k]][d]) + bias[d]
// fedges has ~zero reuse -> load evict-first (__ldcs) so the 51 MB support
// table stays L2-resident. Output stores likewise streamed (__stcs).
// ---------------------------------------------------------------------------
__global__ __launch_bounds__(64) void agg_kernel(
    const float* __restrict__ support,
    const float* __restrict__ fedges,
    const int* __restrict__ a2a,
    const int* __restrict__ n2e,
    const float* __restrict__ bias,
    float* __restrict__ out,
    int M)
{
    const int n = blockIdx.x;
    if (n >= M) return;

    __shared__ int sa[KNEI];
    __shared__ int se[KNEI];

    const int t = threadIdx.x;
    if (t < KNEI) {
        sa[t] = a2a[(size_t)n * KNEI + t];
    } else if (t < 2 * KNEI) {
        se[t - KNEI] = n2e[(size_t)n * KNEI + (t - KNEI)];
    }
    __syncthreads();

    const int off = t * 4;
    float4 acc = make_float4(0.f, 0.f, 0.f, 0.f);

#pragma unroll
    for (int k = 0; k < KNEI; k++) {
        const float4 s = *reinterpret_cast<const float4*>(&support[(size_t)sa[k] * NN_D + off]);
        const float4 f = __ldcs(reinterpret_cast<const float4*>(
            &fedges[(size_t)se[k] * NN_D + off]));
        acc.x += s.x * f.x;
        acc.y += s.y * f.y;
        acc.z += s.z * f.z;
        acc.w += s.w * f.w;
    }

    const float4 bl = *reinterpret_cast<const float4*>(&bias[off]);
    float4 o;
    o.x = tanhf(acc.x) + bl.x;
    o.y = tanhf(acc.y) + bl.y;
    o.z = tanhf(acc.z) + bl.z;
    o.w = tanhf(acc.w) + bl.w;
    __stcs(reinterpret_cast<float4*>(&out[(size_t)n * NN_D + off]), o);
}

// ---------------------------------------------------------------------------
// Launch
// ---------------------------------------------------------------------------
extern "C" void kernel_launch(void* const* d_in, const int* in_sizes, int n_in,
                              void* d_out, int out_size)
{
    const float* x    = (const float*)d_in[0];
    const float* fe   = (const float*)d_in[1];
    const int*   a2a  = (const int*)d_in[2];
    const int*   n2e  = (const int*)d_in[3];
    const float* W    = (const float*)d_in[4];
    const float* blin = (const float*)d_in[5];
    const float* bias = (const float*)d_in[6];
    float*       out  = (float*)d_out;

    const int M = in_sizes[0] / NN_D;               // 50000

    float* sup = nullptr;
    cudaGetSymbolAddress((void**)&sup, g_support);

    cudaFuncSetAttribute(gemm_mma_kernel,
                         cudaFuncAttributeMaxDynamicSharedMemorySize, SMEM_GEMM);

    dim3 ggrid((M + BM - 1) / BM, NN_D / BN);       // (391, 2)
    gemm_mma_kernel<<<ggrid, 256, SMEM_GEMM>>>(x, W, blin, sup, M);

    agg_kernel<<<M, 64>>>(sup, fe, a2a, n2e, bias, out, M);
}

// round 10
// speedup vs baseline: 1.0435x; 1.0435x over previous
#include <cuda_runtime.h>
#include <cuda_fp16.h>
#include <cstdint>

#define NN_D 256          // feature dim D
#define KNEI 16           // neighbors per node

// fp16 support scratch: 50000*256*2 = 25.6 MB (L2-resident for agg)
__device__ __half g_support_h[50000 * 256];
// fp16 pre-converted weights: 256*256*2 = 128 KB
__device__ __half g_Wh[256 * 256];

// ---------------------------------------------------------------------------
// W fp32 -> fp16 pre-pass (one-time, ~1us)
// ---------------------------------------------------------------------------
__global__ __launch_bounds__(256) void cvtW_kernel(const float* __restrict__ W,
                                                   __half* __restrict__ Wh)
{
    const int i = (blockIdx.x * 256 + threadIdx.x) * 4;   // 64 blocks cover 65536
    float4 v = *reinterpret_cast<const float4*>(W + i);
    __half2 h0 = __floats2half2_rn(v.x, v.y);
    __half2 h1 = __floats2half2_rn(v.z, v.w);
    *reinterpret_cast<__half2*>(Wh + i)     = h0;
    *reinterpret_cast<__half2*>(Wh + i + 2) = h1;
}

// ---------------------------------------------------------------------------
// GEMM via mma.sync fp16: A split hi/lo (e5m10 pair ~ fp32 precision), B fp16.
// 2 MMAs per fragment pair: D = Ah*B + Al*B.  Output stored fp16.
// C[M,256] = A[M,256] @ W[256,256]^T + b_lin
// CTA tile 128x128, 8 warps (4M x 2N), warp tile 32x64, K-chunk 64.
// ---------------------------------------------------------------------------
#define BM 128
#define BN 128
#define KC 64
#define LDS 72            // padded fp16 leading dim (conflict-free ldmatrix)

#define AS_H 0
#define AS_L (BM * LDS * 2)            // 18432
#define BS   (2 * BM * LDS * 2)       // 36864
#define SMEM_GEMM (3 * BM * LDS * 2)  // 55296

__device__ __forceinline__ uint32_t smem_u32(const void* p) {
    uint32_t a;
    asm("{ .reg .u64 t; cvta.to.shared.u64 t, %1; cvt.u32.u64 %0, t; }"
        : "=r"(a) : "l"(p));
    return a;
}

// fp16 hi/lo split of a float pair
__device__ __forceinline__ void cvt_hilo_f16(float x, float y, uint32_t& h, uint32_t& l) {
    __half2 hh, ll;
    hh.x = __float2half_rn(x);
    hh.y = __float2half_rn(y);
    ll.x = __float2half_rn(x - __half2float(hh.x));
    ll.y = __float2half_rn(y - __half2float(hh.y));
    h = *reinterpret_cast<uint32_t*>(&hh);
    l = *reinterpret_cast<uint32_t*>(&ll);
}

__device__ __forceinline__ void ldm_x4(uint32_t& r0, uint32_t& r1, uint32_t& r2,
                                       uint32_t& r3, uint32_t addr) {
    asm volatile("ldmatrix.sync.aligned.m8n8.x4.shared.b16 {%0,%1,%2,%3}, [%4];"
                 : "=r"(r0), "=r"(r1), "=r"(r2), "=r"(r3) : "r"(addr));
}

__device__ __forceinline__ void mma16816(float* c, const uint32_t* a, const uint32_t* b) {
    asm volatile(
        "mma.sync.aligned.m16n8k16.row.col.f32.f16.f16.f32 "
        "{%0,%1,%2,%3}, {%4,%5,%6,%7}, {%8,%9}, {%0,%1,%2,%3};"
        : "+f"(c[0]), "+f"(c[1]), "+f"(c[2]), "+f"(c[3])
        : "r"(a[0]), "r"(a[1]), "r"(a[2]), "r"(a[3]), "r"(b[0]), "r"(b[1]));
}

__global__ __launch_bounds__(256) void gemm_mma_kernel(
    const float* __restrict__ A,
    const __half* __restrict__ Wh,
    const float* __restrict__ blin,
    __half* __restrict__ C,
    int M)
{
    extern __shared__ char smem[];
    const uint32_t sbase = smem_u32(smem);
    const int tid  = threadIdx.x;
    const int wid  = tid >> 5;
    const int lane = tid & 31;
    const int warp_m = wid & 3;       // 0..3 -> 32-row slice
    const int warp_n = wid >> 2;      // 0..1 -> 64-col slice
    const int bm = blockIdx.x * BM;
    const int bn = blockIdx.y * BN;

    float acc[2][8][4];
#pragma unroll
    for (int i = 0; i < 2; i++)
#pragma unroll
        for (int j = 0; j < 8; j++)
#pragma unroll
            for (int v = 0; v < 4; v++) acc[i][j][v] = 0.0f;

    // ldmatrix source addresses (per-lane)
    const int a_row = warp_m * 32 + (lane & 15);
    const int a_col = (lane >> 4) * 8;
    const uint32_t a_base = sbase + (uint32_t)(a_row * LDS + a_col) * 2;
    const int b_row_base = warp_n * 64 + ((lane >> 4) << 3) + (lane & 7);
    const int b_col = ((lane >> 3) & 1) * 8;
    const uint32_t b_base = sbase + BS + (uint32_t)(b_row_base * LDS + b_col) * 2;

    for (int c = 0; c < NN_D / KC; c++) {        // 4 K-chunks
        // ---- A: global fp32 -> smem fp16 hi/lo (8 iters/thread) ----
#pragma unroll
        for (int i = tid; i < BM * (KC / 4); i += 256) {
            const int row = i >> 4;              // 0..127
            const int q   = i & 15;              // 0..15 -> k offset q*4
            const int gr  = bm + row;
            float4 v = (gr < M)
                ? *reinterpret_cast<const float4*>(A + (size_t)gr * NN_D + c * KC + q * 4)
                : make_float4(0.f, 0.f, 0.f, 0.f);
            uint32_t h0, l0, h1, l1;
            cvt_hilo_f16(v.x, v.y, h0, l0);
            cvt_hilo_f16(v.z, v.w, h1, l1);
            const uint32_t off = (uint32_t)(row * LDS + q * 4) * 2;
            *reinterpret_cast<uint2*>(smem + AS_H + off) = make_uint2(h0, h1);
            *reinterpret_cast<uint2*>(smem + AS_L + off) = make_uint2(l0, l1);
        }
        // ---- B: pre-converted fp16, pure copy (4 iters/thread) ----
#pragma unroll
        for (int i = tid; i < BM * (KC / 8); i += 256) {
            const int row = i >> 3;              // 0..127
            const int j   = i & 7;               // 8 halves each
            uint4 v = *reinterpret_cast<const uint4*>(
                Wh + (size_t)(bn + row) * NN_D + c * KC + j * 8);
            *reinterpret_cast<uint4*>(smem + BS + (uint32_t)(row * LDS + j * 8) * 2) = v;
        }
        __syncthreads();

        // ---- compute: 4 k-steps of 16 ----
#pragma unroll
        for (int ks = 0; ks < KC / 16; ks++) {
            const uint32_t koff = (uint32_t)(ks * 16) * 2;

            uint32_t ah[2][4], al[2][4];
            ldm_x4(ah[0][0], ah[0][1], ah[0][2], ah[0][3], a_base + AS_H + koff);
            ldm_x4(ah[1][0], ah[1][1], ah[1][2], ah[1][3], a_base + AS_H + koff + 16 * LDS * 2);
            ldm_x4(al[0][0], al[0][1], al[0][2], al[0][3], a_base + AS_L + koff);
            ldm_x4(al[1][0], al[1][1], al[1][2], al[1][3], a_base + AS_L + koff + 16 * LDS * 2);

            uint32_t bf[8][2];
#pragma unroll
            for (int np = 0; np < 4; np++) {
                const uint32_t bo = b_base + koff + (uint32_t)(np * 16 * LDS) * 2;
                ldm_x4(bf[2 * np][0], bf[2 * np][1], bf[2 * np + 1][0], bf[2 * np + 1][1], bo);
            }

#pragma unroll
            for (int mi = 0; mi < 2; mi++) {
#pragma unroll
                for (int nj = 0; nj < 8; nj++) {
                    mma16816(acc[mi][nj], ah[mi], bf[nj]);
                    mma16816(acc[mi][nj], al[mi], bf[nj]);
                }
            }
        }
        __syncthreads();
    }

    // ---- epilogue: + b_lin, store fp16 (normal stores -> stays in L2) ----
    float2 blv[8];
#pragma unroll
    for (int nj = 0; nj < 8; nj++) {
        const int col = bn + warp_n * 64 + nj * 8 + (lane & 3) * 2;
        blv[nj].x = __ldg(blin + col);
        blv[nj].y = __ldg(blin + col + 1);
    }
#pragma unroll
    for (int mi = 0; mi < 2; mi++) {
        const int r0 = bm + warp_m * 32 + mi * 16 + (lane >> 2);
        const int r1 = r0 + 8;
#pragma unroll
        for (int nj = 0; nj < 8; nj++) {
            const int col = bn + warp_n * 64 + nj * 8 + (lane & 3) * 2;
            if (r0 < M) {
                *reinterpret_cast<__half2*>(C + (size_t)r0 * NN_D + col) =
                    __floats2half2_rn(acc[mi][nj][0] + blv[nj].x,
                                      acc[mi][nj][1] + blv[nj].y);
            }
            if (r1 < M) {
                *reinterpret_cast<__half2*>(C + (size_t)r1 * NN_D + col) =
                    __floats2half2_rn(acc[mi][nj][2] + blv[nj].x,
                                      acc[mi][nj][3] + blv[nj].y);
            }
        }
    }
}

// ---------------------------------------------------------------------------
// Aggregation: out[n][d] = tanh(sum_k sup[a2a[n][k]][d] * fe[n2e[n][k]][d]) + bias[d]
// support is fp16 and L2-resident (25.6 MB); fedges streamed evict-first.
// ---------------------------------------------------------------------------
struct alignas(8) half4 { __half2 a, b; };

__global__ __launch_bounds__(64) void agg_kernel(
    const __half* __restrict__ support,
    const float* __restrict__ fedges,
    const int* __restrict__ a2a,
    const int* __restrict__ n2e,
    const float* __restrict__ bias,
    float* __restrict__ out,
    int M)
{
    const int n = blockIdx.x;
    if (n >= M) return;

    __shared__ int sa[KNEI];
    __shared__ int se[KNEI];

    const int t = threadIdx.x;
    if (t < KNEI) {
        sa[t] = a2a[(size_t)n * KNEI + t];
    } else if (t < 2 * KNEI) {
        se[t - KNEI] = n2e[(size_t)n * KNEI + (t - KNEI)];
    }
    __syncthreads();

    const int off = t * 4;
    float4 acc = make_float4(0.f, 0.f, 0.f, 0.f);

#pragma unroll
    for (int k = 0; k < KNEI; k++) {
        const half4 s = *reinterpret_cast<const half4*>(
            &support[(size_t)sa[k] * NN_D + off]);
        const float4 f = __ldcs(reinterpret_cast<const float4*>(
            &fedges[(size_t)se[k] * NN_D + off]));
        const float2 s0 = __half22float2(s.a);
        const float2 s1 = __half22float2(s.b);
        acc.x += s0.x * f.x;
        acc.y += s0.y * f.y;
        acc.z += s1.x * f.z;
        acc.w += s1.y * f.w;
    }

    const float4 bl = *reinterpret_cast<const float4*>(&bias[off]);
    float4 o;
    o.x = tanhf(acc.x) + bl.x;
    o.y = tanhf(acc.y) + bl.y;
    o.z = tanhf(acc.z) + bl.z;
    o.w = tanhf(acc.w) + bl.w;
    __stcs(reinterpret_cast<float4*>(&out[(size_t)n * NN_D + off]), o);
}

// ---------------------------------------------------------------------------
// Launch
// ---------------------------------------------------------------------------
extern "C" void kernel_launch(void* const* d_in, const int* in_sizes, int n_in,
                              void* d_out, int out_size)
{
    const float* x    = (const float*)d_in[0];
    const float* fe   = (const float*)d_in[1];
    const int*   a2a  = (const int*)d_in[2];
    const int*   n2e  = (const int*)d_in[3];
    const float* W    = (const float*)d_in[4];
    const float* blin = (const float*)d_in[5];
    const float* bias = (const float*)d_in[6];
    float*       out  = (float*)d_out;

    const int M = in_sizes[0] / NN_D;               // 50000

    __half* sup = nullptr;
    cudaGetSymbolAddress((void**)&sup, g_support_h);
    __half* Wh = nullptr;
    cudaGetSymbolAddress((void**)&Wh, g_Wh);

    cudaFuncSetAttribute(gemm_mma_kernel,
                         cudaFuncAttributeMaxDynamicSharedMemorySize, SMEM_GEMM);

    cvtW_kernel<<<NN_D * NN_D / 1024, 256>>>(W, Wh);

    dim3 ggrid((M + BM - 1) / BM, NN_D / BN);       // (391, 2)
    gemm_mma_kernel<<<ggrid, 256, SMEM_GEMM>>>(x, Wh, blin, sup, M);

    agg_kernel<<<M, 64>>>(sup, fe, a2a, n2e, bias, out, M);
}

// round 11
// speedup vs baseline: 1.1164x; 1.0699x over previous
#include <cuda_runtime.h>
#include <cuda_fp16.h>
#include <cstdint>

#define NN_D 256          // feature dim D
#define KNEI 16           // neighbors per node

// fp16 support scratch: 50000*256*2 = 25.6 MB (L2-resident for agg)
__device__ __half g_support_h[50000 * 256];

// ---------------------------------------------------------------------------
// GEMM via mma.sync fp16: A split hi/lo (~fp32 precision), B fp16 (2^-11 eps).
// 2 MMAs per fragment pair: D = Ah*B + Al*B.  Output stored fp16.
// Software-pipelined: chunk c+1 global loads prefetched to registers before
// chunk c's MMAs, hiding LDG latency behind tensor work.
// C[M,256] = A[M,256] @ W[256,256]^T + b_lin
// CTA tile 128x128, 8 warps (4M x 2N), warp tile 32x64, K-chunk 64.
// ---------------------------------------------------------------------------
#define BM 128
#define BN 128
#define KC 64
#define LDS 72            // padded fp16 leading dim (conflict-free ldmatrix)

#define AS_H 0
#define AS_L (BM * LDS * 2)            // 18432
#define BS   (2 * BM * LDS * 2)       // 36864
#define SMEM_GEMM (3 * BM * LDS * 2)  // 55296

__device__ __forceinline__ uint32_t smem_u32(const void* p) {
    uint32_t a;
    asm("{ .reg .u64 t; cvta.to.shared.u64 t, %1; cvt.u32.u64 %0, t; }"
        : "=r"(a) : "l"(p));
    return a;
}

// fp16 hi/lo split of a float pair
__device__ __forceinline__ void cvt_hilo_f16(float x, float y, uint32_t& h, uint32_t& l) {
    __half2 hh, ll;
    hh.x = __float2half_rn(x);
    hh.y = __float2half_rn(y);
    ll.x = __float2half_rn(x - __half2float(hh.x));
    ll.y = __float2half_rn(y - __half2float(hh.y));
    h = *reinterpret_cast<uint32_t*>(&hh);
    l = *reinterpret_cast<uint32_t*>(&ll);
}

__device__ __forceinline__ uint32_t cvt_f16x2(float x, float y) {
    __half2 hh;
    hh.x = __float2half_rn(x);
    hh.y = __float2half_rn(y);
    return *reinterpret_cast<uint32_t*>(&hh);
}

__device__ __forceinline__ void ldm_x4(uint32_t& r0, uint32_t& r1, uint32_t& r2,
                                       uint32_t& r3, uint32_t addr) {
    asm volatile("ldmatrix.sync.aligned.m8n8.x4.shared.b16 {%0,%1,%2,%3}, [%4];"
                 : "=r"(r0), "=r"(r1), "=r"(r2), "=r"(r3) : "r"(addr));
}

__device__ __forceinline__ void mma16816(float* c, const uint32_t* a, const uint32_t* b) {
    asm volatile(
        "mma.sync.aligned.m16n8k16.row.col.f32.f16.f16.f32 "
        "{%0,%1,%2,%3}, {%4,%5,%6,%7}, {%8,%9}, {%0,%1,%2,%3};"
        : "+f"(c[0]), "+f"(c[1]), "+f"(c[2]), "+f"(c[3])
        : "r"(a[0]), "r"(a[1]), "r"(a[2]), "r"(a[3]), "r"(b[0]), "r"(b[1]));
}

__global__ __launch_bounds__(256, 1) void gemm_mma_kernel(
    const float* __restrict__ A,
    const float* __restrict__ W,
    const float* __restrict__ blin,
    __half* __restrict__ C,
    int M)
{
    extern __shared__ char smem[];
    const uint32_t sbase = smem_u32(smem);
    const int tid  = threadIdx.x;
    const int wid  = tid >> 5;
    const int lane = tid & 31;
    const int warp_m = wid & 3;       // 0..3 -> 32-row slice
    const int warp_n = wid >> 2;      // 0..1 -> 64-col slice
    const int bm = blockIdx.x * BM;
    const int bn = blockIdx.y * BN;

    float acc[2][8][4];
#pragma unroll
    for (int i = 0; i < 2; i++)
#pragma unroll
        for (int j = 0; j < 8; j++)
#pragma unroll
            for (int v = 0; v < 4; v++) acc[i][j][v] = 0.0f;

    // Per-thread staging coordinates (8 units each for A and B)
    int srow[8], sq[8];
#pragma unroll
    for (int k = 0; k < 8; k++) {
        const int i = tid + k * 256;
        srow[k] = i >> 4;             // 0..127
        sq[k]   = (i & 15) * 4;       // k-offset within chunk
    }

    // ldmatrix source addresses (per-lane)
    const int a_row = warp_m * 32 + (lane & 15);
    const int a_col = (lane >> 4) * 8;
    const uint32_t a_base = sbase + (uint32_t)(a_row * LDS + a_col) * 2;
    const int b_row_base = warp_n * 64 + ((lane >> 4) << 3) + (lane & 7);
    const int b_col = ((lane >> 3) & 1) * 8;
    const uint32_t b_base = sbase + BS + (uint32_t)(b_row_base * LDS + b_col) * 2;

    // ---- prologue: prefetch chunk 0 into registers ----
    float4 av[8], wv[8];
#pragma unroll
    for (int k = 0; k < 8; k++) {
        const int gr = bm + srow[k];
        av[k] = (gr < M)
            ? *reinterpret_cast<const float4*>(A + (size_t)gr * NN_D + sq[k])
            : make_float4(0.f, 0.f, 0.f, 0.f);
        wv[k] = *reinterpret_cast<const float4*>(W + (size_t)(bn + srow[k]) * NN_D + sq[k]);
    }

    for (int c = 0; c < NN_D / KC; c++) {        // 4 K-chunks
        // ---- convert prefetched regs -> smem ----
#pragma unroll
        for (int k = 0; k < 8; k++) {
            uint32_t h0, l0, h1, l1;
            cvt_hilo_f16(av[k].x, av[k].y, h0, l0);
            cvt_hilo_f16(av[k].z, av[k].w, h1, l1);
            const uint32_t off = (uint32_t)(srow[k] * LDS + sq[k]) * 2;
            *reinterpret_cast<uint2*>(smem + AS_H + off) = make_uint2(h0, h1);
            *reinterpret_cast<uint2*>(smem + AS_L + off) = make_uint2(l0, l1);
            *reinterpret_cast<uint2*>(smem + BS + off) =
                make_uint2(cvt_f16x2(wv[k].x, wv[k].y), cvt_f16x2(wv[k].z, wv[k].w));
        }
        __syncthreads();

        // ---- prefetch chunk c+1 (LDGs issue now, consumed next iteration;
        //      latency hidden behind the MMAs below) ----
        if (c < NN_D / KC - 1) {
            const int ko = (c + 1) * KC;
#pragma unroll
            for (int k = 0; k < 8; k++) {
                const int gr = bm + srow[k];
                av[k] = (gr < M)
                    ? *reinterpret_cast<const float4*>(A + (size_t)gr * NN_D + ko + sq[k])
                    : make_float4(0.f, 0.f, 0.f, 0.f);
                wv[k] = *reinterpret_cast<const float4*>(
                    W + (size_t)(bn + srow[k]) * NN_D + ko + sq[k]);
            }
        }

        // ---- compute: 4 k-steps of 16 ----
#pragma unroll
        for (int ks = 0; ks < KC / 16; ks++) {
            const uint32_t koff = (uint32_t)(ks * 16) * 2;

            uint32_t ah[2][4], al[2][4];
            ldm_x4(ah[0][0], ah[0][1], ah[0][2], ah[0][3], a_base + AS_H + koff);
            ldm_x4(ah[1][0], ah[1][1], ah[1][2], ah[1][3], a_base + AS_H + koff + 16 * LDS * 2);
            ldm_x4(al[0][0], al[0][1], al[0][2], al[0][3], a_base + AS_L + koff);
            ldm_x4(al[1][0], al[1][1], al[1][2], al[1][3], a_base + AS_L + koff + 16 * LDS * 2);

            uint32_t bf[8][2];
#pragma unroll
            for (int np = 0; np < 4; np++) {
                const uint32_t bo = b_base + koff + (uint32_t)(np * 16 * LDS) * 2;
                ldm_x4(bf[2 * np][0], bf[2 * np][1], bf[2 * np + 1][0], bf[2 * np + 1][1], bo);
            }

#pragma unroll
            for (int mi = 0; mi < 2; mi++) {
#pragma unroll
                for (int nj = 0; nj < 8; nj++) {
                    mma16816(acc[mi][nj], ah[mi], bf[nj]);
                    mma16816(acc[mi][nj], al[mi], bf[nj]);
                }
            }
        }
        __syncthreads();
    }

    // ---- epilogue: + b_lin, store fp16 ----
    float2 blv[8];
#pragma unroll
    for (int nj = 0; nj < 8; nj++) {
        const int col = bn + warp_n * 64 + nj * 8 + (lane & 3) * 2;
        blv[nj].x = __ldg(blin + col);
        blv[nj].y = __ldg(blin + col + 1);
    }
#pragma unroll
    for (int mi = 0; mi < 2; mi++) {
        const int r0 = bm + warp_m * 32 + mi * 16 + (lane >> 2);
        const int r1 = r0 + 8;
#pragma unroll
        for (int nj = 0; nj < 8; nj++) {
            const int col = bn + warp_n * 64 + nj * 8 + (lane & 3) * 2;
            if (r0 < M) {
                *reinterpret_cast<__half2*>(C + (size_t)r0 * NN_D + col) =
                    __floats2half2_rn(acc[mi][nj][0] + blv[nj].x,
                                      acc[mi][nj][1] + blv[nj].y);
            }
            if (r1 < M) {
                *reinterpret_cast<__half2*>(C + (size_t)r1 * NN_D + col) =
                    __floats2half2_rn(acc[mi][nj][2] + blv[nj].x,
                                      acc[mi][nj][3] + blv[nj].y);
            }
        }
    }
}

// ---------------------------------------------------------------------------
// Aggregation: out[n][d] = tanh(sum_k sup[a2a[n][k]][d] * fe[n2e[n][k]][d]) + bias[d]
// support is fp16 (25.6 MB, L2-resident); fedges streamed evict-first.
// ---------------------------------------------------------------------------
struct alignas(8) half4 { __half2 a, b; };

__global__ __launch_bounds__(64) void agg_kernel(
    const __half* __restrict__ support,
    const float* __restrict__ fedges,
    const int* __restrict__ a2a,
    const int* __restrict__ n2e,
    const float* __restrict__ bias,
    float* __restrict__ out,
    int M)
{
    const int n = blockIdx.x;
    if (n >= M) return;

    __shared__ int sa[KNEI];
    __shared__ int se[KNEI];

    const int t = threadIdx.x;
    if (t < KNEI) {
        sa[t] = a2a[(size_t)n * KNEI + t];
    } else if (t < 2 * KNEI) {
        se[t - KNEI] = n2e[(size_t)n * KNEI + (t - KNEI)];
    }
    __syncthreads();

    const int off = t * 4;
    float4 acc = make_float4(0.f, 0.f, 0.f, 0.f);

#pragma unroll
    for (int k = 0; k < KNEI; k++) {
        const half4 s = *reinterpret_cast<const half4*>(
            &support[(size_t)sa[k] * NN_D + off]);
        const float4 f = __ldcs(reinterpret_cast<const float4*>(
            &fedges[(size_t)se[k] * NN_D + off]));
        const float2 s0 = __half22float2(s.a);
        const float2 s1 = __half22float2(s.b);
        acc.x += s0.x * f.x;
        acc.y += s0.y * f.y;
        acc.z += s1.x * f.z;
        acc.w += s1.y * f.w;
    }

    const float4 bl = *reinterpret_cast<const float4*>(&bias[off]);
    float4 o;
    o.x = tanhf(acc.x) + bl.x;
    o.y = tanhf(acc.y) + bl.y;
    o.z = tanhf(acc.z) + bl.z;
    o.w = tanhf(acc.w) + bl.w;
    __stcs(reinterpret_cast<float4*>(&out[(size_t)n * NN_D + off]), o);
}

// ---------------------------------------------------------------------------
// Launch
// ---------------------------------------------------------------------------
extern "C" void kernel_launch(void* const* d_in, const int* in_sizes, int n_in,
                              void* d_out, int out_size)
{
    const float* x    = (const float*)d_in[0];
    const float* fe   = (const float*)d_in[1];
    const int*   a2a  = (const int*)d_in[2];
    const int*   n2e  = (const int*)d_in[3];
    const float* W    = (const float*)d_in[4];
    const float* blin = (const float*)d_in[5];
    const float* bias = (const float*)d_in[6];
    float*       out  = (float*)d_out;

    const int M = in_sizes[0] / NN_D;               // 50000

    __half* sup = nullptr;
    cudaGetSymbolAddress((void**)&sup, g_support_h);

    cudaFuncSetAttribute(gemm_mma_kernel,
                         cudaFuncAttributeMaxDynamicSharedMemorySize, SMEM_GEMM);

    dim3 ggrid((M + BM - 1) / BM, NN_D / BN);       // (391, 2)
    gemm_mma_kernel<<<ggrid, 256, SMEM_GEMM>>>(x, W, blin, sup, M);

    agg_kernel<<<M, 64>>>(sup, fe, a2a, n2e, bias, out, M);
}

// round 14
// speedup vs baseline: 1.1346x; 1.0163x over previous
#include <cuda_runtime.h>
#include <cuda_fp16.h>
#include <cstdint>

#define NN_D 256          // feature dim D
#define KNEI 16           // neighbors per node

// fp16 support scratch: 50000*256*2 = 25.6 MB (L2-resident for agg)
__device__ __half g_support_h[50000 * 256];

// ---------------------------------------------------------------------------
// GEMM via mma.sync fp16: A split hi/lo (~fp32 precision), B fp16 (2^-11 eps).
// 2 MMAs per fragment pair: D = Ah*B + Al*B.  Output stored fp16.
// CTA tile 128x64 (8 warps = 4M x 2N, warp tile 32x32), KC=64, ~119 regs ->
// 2 CTAs/SM so staging of one CTA overlaps MMAs of the other.
// ---------------------------------------------------------------------------
#define BM 128
#define BN 64
#define KC 64
#define LDS 72            // padded fp16 leading dim (conflict-free ldmatrix)

#define AS_H 0
#define AS_L (BM * LDS * 2)                  // 18432
#define BS   (2 * BM * LDS * 2)              // 36864
#define SMEM_GEMM (BS + BN * LDS * 2)        // 46080

__device__ __forceinline__ uint32_t smem_u32(const void* p) {
    uint32_t a;
    asm("{ .reg .u64 t; cvta.to.shared.u64 t, %1; cvt.u32.u64 %0, t; }"
        : "=r"(a) : "l"(p));
    return a;
}

// fp16 hi/lo split of a float pair
__device__ __forceinline__ void cvt_hilo_f16(float x, float y, uint32_t& h, uint32_t& l) {
    __half2 hh, ll;
    hh.x = __float2half_rn(x);
    hh.y = __float2half_rn(y);
    ll.x = __float2half_rn(x - __half2float(hh.x));
    ll.y = __float2half_rn(y - __half2float(hh.y));
    h = *reinterpret_cast<uint32_t*>(&hh);
    l = *reinterpret_cast<uint32_t*>(&ll);
}

__device__ __forceinline__ uint32_t cvt_f16x2(float x, float y) {
    __half2 hh;
    hh.x = __float2half_rn(x);
    hh.y = __float2half_rn(y);
    return *reinterpret_cast<uint32_t*>(&hh);
}

__device__ __forceinline__ void ldm_x4(uint32_t& r0, uint32_t& r1, uint32_t& r2,
                                       uint32_t& r3, uint32_t addr) {
    asm volatile("ldmatrix.sync.aligned.m8n8.x4.shared.b16 {%0,%1,%2,%3}, [%4];"
                 : "=r"(r0), "=r"(r1), "=r"(r2), "=r"(r3) : "r"(addr));
}

__device__ __forceinline__ void mma16816(float* c, const uint32_t* a, const uint32_t* b) {
    asm volatile(
        "mma.sync.aligned.m16n8k16.row.col.f32.f16.f16.f32 "
        "{%0,%1,%2,%3}, {%4,%5,%6,%7}, {%8,%9}, {%0,%1,%2,%3};"
        : "+f"(c[0]), "+f"(c[1]), "+f"(c[2]), "+f"(c[3])
        : "r"(a[0]), "r"(a[1]), "r"(a[2]), "r"(a[3]), "r"(b[0]), "r"(b[1]));
}

__global__ __launch_bounds__(256, 2) void gemm_mma_kernel(
    const float* __restrict__ A,
    const float* __restrict__ W,
    const float* __restrict__ blin,
    __half* __restrict__ C,
    int M)
{
    extern __shared__ char smem[];
    const uint32_t sbase = smem_u32(smem);
    const int tid  = threadIdx.x;
    const int wid  = tid >> 5;
    const int lane = tid & 31;
    const int warp_m = wid & 3;       // 0..3 -> 32-row slice
    const int warp_n = wid >> 2;      // 0..1 -> 32-col slice
    const int bm = blockIdx.x * BM;
    const int bn = blockIdx.y * BN;

    float acc[2][4][4];
#pragma unroll
    for (int i = 0; i < 2; i++)
#pragma unroll
        for (int j = 0; j < 4; j++)
#pragma unroll
            for (int v = 0; v < 4; v++) acc[i][j][v] = 0.0f;

    // Staging coordinates: A = 2048 float4 units (8/thread), B = 1024 (4/thread)
    const int arow0 = tid >> 4;           // A: rows tid>>4, +16 each iter... (see loop)
    const int aq    = (tid & 15) * 4;

    // ldmatrix source addresses (per-lane)
    const int a_row = warp_m * 32 + (lane & 15);
    const int a_col = (lane >> 4) * 8;
    const uint32_t a_base = sbase + (uint32_t)(a_row * LDS + a_col) * 2;
    const int b_row_base = warp_n * 32 + ((lane >> 4) << 3) + (lane & 7);
    const int b_col = ((lane >> 3) & 1) * 8;
    const uint32_t b_base = sbase + BS + (uint32_t)(b_row_base * LDS + b_col) * 2;

    // ---- prologue: prefetch chunk 0 ----
    float4 av[8], wv[4];
#pragma unroll
    for (int k = 0; k < 8; k++) {
        const int gr = bm + arow0 + k * 16;
        av[k] = (gr < M)
            ? *reinterpret_cast<const float4*>(A + (size_t)gr * NN_D + aq)
            : make_float4(0.f, 0.f, 0.f, 0.f);
    }
#pragma unroll
    for (int k = 0; k < 4; k++) {
        wv[k] = *reinterpret_cast<const float4*>(
            W + (size_t)(bn + arow0 + k * 16) * NN_D + aq);
    }

    for (int c = 0; c < NN_D / KC; c++) {        // 4 K-chunks
        // ---- convert prefetched regs -> smem ----
#pragma unroll
        for (int k = 0; k < 8; k++) {
            uint32_t h0, l0, h1, l1;
            cvt_hilo_f16(av[k].x, av[k].y, h0, l0);
            cvt_hilo_f16(av[k].z, av[k].w, h1, l1);
            const uint32_t off = (uint32_t)((arow0 + k * 16) * LDS + aq) * 2;
            *reinterpret_cast<uint2*>(smem + AS_H + off) = make_uint2(h0, h1);
            *reinterpret_cast<uint2*>(smem + AS_L + off) = make_uint2(l0, l1);
        }
#pragma unroll
        for (int k = 0; k < 4; k++) {
            const uint32_t off = (uint32_t)((arow0 + k * 16) * LDS + aq) * 2;
            *reinterpret_cast<uint2*>(smem + BS + off) =
                make_uint2(cvt_f16x2(wv[k].x, wv[k].y), cvt_f16x2(wv[k].z, wv[k].w));
        }
        __syncthreads();

        // ---- prefetch chunk c+1 (hidden behind MMAs below) ----
        if (c < NN_D / KC - 1) {
            const int ko = (c + 1) * KC;
#pragma unroll
            for (int k = 0; k < 8; k++) {
                const int gr = bm + arow0 + k * 16;
                av[k] = (gr < M)
                    ? *reinterpret_cast<const float4*>(A + (size_t)gr * NN_D + ko + aq)
                    : make_float4(0.f, 0.f, 0.f, 0.f);
            }
#pragma unroll
            for (int k = 0; k < 4; k++) {
                wv[k] = *reinterpret_cast<const float4*>(
                    W + (size_t)(bn + arow0 + k * 16) * NN_D + ko + aq);
            }
        }

        // ---- compute: 4 k-steps of 16 ----
#pragma unroll
        for (int ks = 0; ks < KC / 16; ks++) {
            const uint32_t koff = (uint32_t)(ks * 16) * 2;

            uint32_t ah[2][4], al[2][4];
            ldm_x4(ah[0][0], ah[0][1], ah[0][2], ah[0][3], a_base + AS_H + koff);
            ldm_x4(ah[1][0], ah[1][1], ah[1][2], ah[1][3], a_base + AS_H + koff + 16 * LDS * 2);
            ldm_x4(al[0][0], al[0][1], al[0][2], al[0][3], a_base + AS_L + koff);
            ldm_x4(al[1][0], al[1][1], al[1][2], al[1][3], a_base + AS_L + koff + 16 * LDS * 2);

            uint32_t bf[4][2];
#pragma unroll
            for (int np = 0; np < 2; np++) {
                const uint32_t bo = b_base + koff + (uint32_t)(np * 16 * LDS) * 2;
                ldm_x4(bf[2 * np][0], bf[2 * np][1], bf[2 * np + 1][0], bf[2 * np + 1][1], bo);
            }

#pragma unroll
            for (int mi = 0; mi < 2; mi++) {
#pragma unroll
                for (int nj = 0; nj < 4; nj++) {
                    mma16816(acc[mi][nj], ah[mi], bf[nj]);
                    mma16816(acc[mi][nj], al[mi], bf[nj]);
                }
            }
        }
        __syncthreads();
    }

    // ---- epilogue: + b_lin, store fp16 ----
    float2 blv[4];
#pragma unroll
    for (int nj = 0; nj < 4; nj++) {
        const int col = bn + warp_n * 32 + nj * 8 + (lane & 3) * 2;
        blv[nj].x = __ldg(blin + col);
        blv[nj].y = __ldg(blin + col + 1);
    }
#pragma unroll
    for (int mi = 0; mi < 2; mi++) {
        const int r0 = bm + warp_m * 32 + mi * 16 + (lane >> 2);
        const int r1 = r0 + 8;
#pragma unroll
        for (int nj = 0; nj < 4; nj++) {
            const int col = bn + warp_n * 32 + nj * 8 + (lane & 3) * 2;
            if (r0 < M) {
                *reinterpret_cast<__half2*>(C + (size_t)r0 * NN_D + col) =
                    __floats2half2_rn(acc[mi][nj][0] + blv[nj].x,
                                      acc[mi][nj][1] + blv[nj].y);
            }
            if (r1 < M) {
                *reinterpret_cast<__half2*>(C + (size_t)r1 * NN_D + col) =
                    __floats2half2_rn(acc[mi][nj][2] + blv[nj].x,
                                      acc[mi][nj][3] + blv[nj].y);
            }
        }
    }
}

// ---------------------------------------------------------------------------
// Aggregation: out[n][d] = tanh(sum_k sup[a2a[n][k]][d] * fe[n2e[n][k]][d]) + bias[d]
// support is fp16 (25.6 MB, L2-resident); fedges streamed evict-first.
// ---------------------------------------------------------------------------
struct alignas(8) half4 { __half2 a, b; };

__global__ __launch_bounds__(64) void agg_kernel(
    const __half* __restrict__ support,
    const float* __restrict__ fedges,
    const int* __restrict__ a2a,
    const int* __restrict__ n2e,
    const float* __restrict__ bias,
    float* __restrict__ out,
    int M)
{
    const int n = blockIdx.x;
    if (n >= M) return;

    __shared__ int sa[KNEI];
    __shared__ int se[KNEI];

    const int t = threadIdx.x;
    if (t < KNEI) {
        sa[t] = a2a[(size_t)n * KNEI + t];
    } else if (t < 2 * KNEI) {
        se[t - KNEI] = n2e[(size_t)n * KNEI + (t - KNEI)];
    }
    __syncthreads();

    const int off = t * 4;
    float4 acc = make_float4(0.f, 0.f, 0.f, 0.f);

#pragma unroll
    for (int k = 0; k < KNEI; k++) {
        const half4 s = *reinterpret_cast<const half4*>(
            &support[(size_t)sa[k] * NN_D + off]);
        const float4 f = __ldcs(reinterpret_cast<const float4*>(
            &fedges[(size_t)se[k] * NN_D + off]));
        const float2 s0 = __half22float2(s.a);
        const float2 s1 = __half22float2(s.b);
        acc.x += s0.x * f.x;
        acc.y += s0.y * f.y;
        acc.z += s1.x * f.z;
        acc.w += s1.y * f.w;
    }

    const float4 bl = *reinterpret_cast<const float4*>(&bias[off]);
    float4 o;
    o.x = tanhf(acc.x) + bl.x;
    o.y = tanhf(acc.y) + bl.y;
    o.z = tanhf(acc.z) + bl.z;
    o.w = tanhf(acc.w) + bl.w;
    __stcs(reinterpret_cast<float4*>(&out[(size_t)n * NN_D + off]), o);
}

// ---------------------------------------------------------------------------
// Launch
// ---------------------------------------------------------------------------
extern "C" void kernel_launch(void* const* d_in, const int* in_sizes, int n_in,
                              void* d_out, int out_size)
{
    const float* x    = (const float*)d_in[0];
    const float* fe   = (const float*)d_in[1];
    const int*   a2a  = (const int*)d_in[2];
    const int*   n2e  = (const int*)d_in[3];
    const float* W    = (const float*)d_in[4];
    const float* blin = (const float*)d_in[5];
    const float* bias = (const float*)d_in[6];
    float*       out  = (float*)d_out;

    const int M = in_sizes[0] / NN_D;               // 50000

    __half* sup = nullptr;
    cudaGetSymbolAddress((void**)&sup, g_support_h);

    cudaFuncSetAttribute(gemm_mma_kernel,
                         cudaFuncAttributeMaxDynamicSharedMemorySize, SMEM_GEMM);

    dim3 ggrid((M + BM - 1) / BM, NN_D / BN);       // (391, 4)
    gemm_mma_kernel<<<ggrid, 256, SMEM_GEMM>>>(x, W, blin, sup, M);

    agg_kernel<<<M, 64>>>(sup, fe, a2a, n2e, bias, out, M);
}

// round 15
// speedup vs baseline: 1.2022x; 1.0595x over previous
#include <cuda_runtime.h>
#include <cuda_fp16.h>
#include <cstdint>

#define NN_D 256          // feature dim D
#define KNEI 16           // neighbors per node

// fp16 support scratch: 50000*256*2 = 25.6 MB (L2-resident for agg)
__device__ __half g_support_h[50000 * 256];

// ---------------------------------------------------------------------------
// GEMM via mma.sync fp16, single MMA per fragment (A, B, support all fp16;
// independent 2^-11 roundings -> rel_err ~5.7e-4 < 1e-3, fp32 accumulate).
// Register-prefetch pipeline + 2 CTAs/SM for cross-CTA latency hiding.
// C[M,256] = A[M,256] @ W[256,256]^T + b_lin
// CTA tile 128x64 (8 warps = 4M x 2N, warp tile 32x32), KC=64.
// ---------------------------------------------------------------------------
#define BM 128
#define BN 64
#define KC 64
#define LDS 72            // padded fp16 leading dim (conflict-free ldmatrix)

#define AS   0
#define BS   (BM * LDS * 2)                  // 18432
#define SMEM_GEMM (BS + BN * LDS * 2)        // 27648

__device__ __forceinline__ uint32_t smem_u32(const void* p) {
    uint32_t a;
    asm("{ .reg .u64 t; cvta.to.shared.u64 t, %1; cvt.u32.u64 %0, t; }"
        : "=r"(a) : "l"(p));
    return a;
}

__device__ __forceinline__ uint32_t cvt_f16x2(float x, float y) {
    __half2 hh;
    hh.x = __float2half_rn(x);
    hh.y = __float2half_rn(y);
    return *reinterpret_cast<uint32_t*>(&hh);
}

__device__ __forceinline__ void ldm_x4(uint32_t& r0, uint32_t& r1, uint32_t& r2,
                                       uint32_t& r3, uint32_t addr) {
    asm volatile("ldmatrix.sync.aligned.m8n8.x4.shared.b16 {%0,%1,%2,%3}, [%4];"
                 : "=r"(r0), "=r"(r1), "=r"(r2), "=r"(r3) : "r"(addr));
}

__device__ __forceinline__ void mma16816(float* c, const uint32_t* a, const uint32_t* b) {
    asm volatile(
        "mma.sync.aligned.m16n8k16.row.col.f32.f16.f16.f32 "
        "{%0,%1,%2,%3}, {%4,%5,%6,%7}, {%8,%9}, {%0,%1,%2,%3};"
        : "+f"(c[0]), "+f"(c[1]), "+f"(c[2]), "+f"(c[3])
        : "r"(a[0]), "r"(a[1]), "r"(a[2]), "r"(a[3]), "r"(b[0]), "r"(b[1]));
}

__global__ __launch_bounds__(256, 2) void gemm_mma_kernel(
    const float* __restrict__ A,
    const float* __restrict__ W,
    const float* __restrict__ blin,
    __half* __restrict__ C,
    int M)
{
    extern __shared__ char smem[];
    const uint32_t sbase = smem_u32(smem);
    const int tid  = threadIdx.x;
    const int wid  = tid >> 5;
    const int lane = tid & 31;
    const int warp_m = wid & 3;       // 0..3 -> 32-row slice
    const int warp_n = wid >> 2;      // 0..1 -> 32-col slice
    const int bm = blockIdx.x * BM;
    const int bn = blockIdx.y * BN;

    float acc[2][4][4];
#pragma unroll
    for (int i = 0; i < 2; i++)
#pragma unroll
        for (int j = 0; j < 4; j++)
#pragma unroll
            for (int v = 0; v < 4; v++) acc[i][j][v] = 0.0f;

    // Staging coordinates: A = 2048 float4 units (8/thread), B = 1024 (4/thread)
    const int arow0 = tid >> 4;
    const int aq    = (tid & 15) * 4;

    // ldmatrix source addresses (per-lane)
    const int a_row = warp_m * 32 + (lane & 15);
    const int a_col = (lane >> 4) * 8;
    const uint32_t a_base = sbase + AS + (uint32_t)(a_row * LDS + a_col) * 2;
    const int b_row_base = warp_n * 32 + ((lane >> 4) << 3) + (lane & 7);
    const int b_col = ((lane >> 3) & 1) * 8;
    const uint32_t b_base = sbase + BS + (uint32_t)(b_row_base * LDS + b_col) * 2;

    // ---- prologue: prefetch chunk 0 ----
    float4 av[8], wv[4];
#pragma unroll
    for (int k = 0; k < 8; k++) {
        const int gr = bm + arow0 + k * 16;
        av[k] = (gr < M)
            ? *reinterpret_cast<const float4*>(A + (size_t)gr * NN_D + aq)
            : make_float4(0.f, 0.f, 0.f, 0.f);
    }
#pragma unroll
    for (int k = 0; k < 4; k++) {
        wv[k] = *reinterpret_cast<const float4*>(
            W + (size_t)(bn + arow0 + k * 16) * NN_D + aq);
    }

    for (int c = 0; c < NN_D / KC; c++) {        // 4 K-chunks
        // ---- convert prefetched regs -> smem (single fp16) ----
#pragma unroll
        for (int k = 0; k < 8; k++) {
            const uint32_t off = (uint32_t)((arow0 + k * 16) * LDS + aq) * 2;
            *reinterpret_cast<uint2*>(smem + AS + off) =
                make_uint2(cvt_f16x2(av[k].x, av[k].y), cvt_f16x2(av[k].z, av[k].w));
        }
#pragma unroll
        for (int k = 0; k < 4; k++) {
            const uint32_t off = (uint32_t)((arow0 + k * 16) * LDS + aq) * 2;
            *reinterpret_cast<uint2*>(smem + BS + off) =
                make_uint2(cvt_f16x2(wv[k].x, wv[k].y), cvt_f16x2(wv[k].z, wv[k].w));
        }
        __syncthreads();

        // ---- prefetch chunk c+1 (hidden behind MMAs / other CTA) ----
        if (c < NN_D / KC - 1) {
            const int ko = (c + 1) * KC;
#pragma unroll
            for (int k = 0; k < 8; k++) {
                const int gr = bm + arow0 + k * 16;
                av[k] = (gr < M)
                    ? *reinterpret_cast<const float4*>(A + (size_t)gr * NN_D + ko + aq)
                    : make_float4(0.f, 0.f, 0.f, 0.f);
            }
#pragma unroll
            for (int k = 0; k < 4; k++) {
                wv[k] = *reinterpret_cast<const float4*>(
                    W + (size_t)(bn + arow0 + k * 16) * NN_D + ko + aq);
            }
        }

        // ---- compute: 4 k-steps of 16 ----
#pragma unroll
        for (int ks = 0; ks < KC / 16; ks++) {
            const uint32_t koff = (uint32_t)(ks * 16) * 2;

            uint32_t af[2][4];
            ldm_x4(af[0][0], af[0][1], af[0][2], af[0][3], a_base + koff);
            ldm_x4(af[1][0], af[1][1], af[1][2], af[1][3], a_base + koff + 16 * LDS * 2);

            uint32_t bf[4][2];
#pragma unroll
            for (int np = 0; np < 2; np++) {
                const uint32_t bo = b_base + koff + (uint32_t)(np * 16 * LDS) * 2;
                ldm_x4(bf[2 * np][0], bf[2 * np][1], bf[2 * np + 1][0], bf[2 * np + 1][1], bo);
            }

#pragma unroll
            for (int mi = 0; mi < 2; mi++) {
#pragma unroll
                for (int nj = 0; nj < 4; nj++) {
                    mma16816(acc[mi][nj], af[mi], bf[nj]);
                }
            }
        }
        __syncthreads();
    }

    // ---- epilogue: + b_lin, store fp16 ----
    float2 blv[4];
#pragma unroll
    for (int nj = 0; nj < 4; nj++) {
        const int col = bn + warp_n * 32 + nj * 8 + (lane & 3) * 2;
        blv[nj].x = __ldg(blin + col);
        blv[nj].y = __ldg(blin + col + 1);
    }
#pragma unroll
    for (int mi = 0; mi < 2; mi++) {
        const int r0 = bm + warp_m * 32 + mi * 16 + (lane >> 2);
        const int r1 = r0 + 8;
#pragma unroll
        for (int nj = 0; nj < 4; nj++) {
            const int col = bn + warp_n * 32 + nj * 8 + (lane & 3) * 2;
            if (r0 < M) {
                *reinterpret_cast<__half2*>(C + (size_t)r0 * NN_D + col) =
                    __floats2half2_rn(acc[mi][nj][0] + blv[nj].x,
                                      acc[mi][nj][1] + blv[nj].y);
            }
            if (r1 < M) {
                *reinterpret_cast<__half2*>(C + (size_t)r1 * NN_D + col) =
                    __floats2half2_rn(acc[mi][nj][2] + blv[nj].x,
                                      acc[mi][nj][3] + blv[nj].y);
            }
        }
    }
}

// ---------------------------------------------------------------------------
// Aggregation: out[n][d] = tanh(sum_k sup[a2a[n][k]][d] * fe[n2e[n][k]][d]) + bias[d]
// support is fp16 (25.6 MB, L2-resident); fedges streamed evict-first.
// ---------------------------------------------------------------------------
struct alignas(8) half4 { __half2 a, b; };

__global__ __launch_bounds__(64) void agg_kernel(
    const __half* __restrict__ support,
    const float* __restrict__ fedges,
    const int* __restrict__ a2a,
    const int* __restrict__ n2e,
    const float* __restrict__ bias,
    float* __restrict__ out,
    int M)
{
    const int n = blockIdx.x;
    if (n >= M) return;

    __shared__ int sa[KNEI];
    __shared__ int se[KNEI];

    const int t = threadIdx.x;
    if (t < KNEI) {
        sa[t] = a2a[(size_t)n * KNEI + t];
    } else if (t < 2 * KNEI) {
        se[t - KNEI] = n2e[(size_t)n * KNEI + (t - KNEI)];
    }
    __syncthreads();

    const int off = t * 4;
    float4 acc = make_float4(0.f, 0.f, 0.f, 0.f);

#pragma unroll
    for (int k = 0; k < KNEI; k++) {
        const half4 s = *reinterpret_cast<const half4*>(
            &support[(size_t)sa[k] * NN_D + off]);
        const float4 f = __ldcs(reinterpret_cast<const float4*>(
            &fedges[(size_t)se[k] * NN_D + off]));
        const float2 s0 = __half22float2(s.a);
        const float2 s1 = __half22float2(s.b);
        acc.x += s0.x * f.x;
        acc.y += s0.y * f.y;
        acc.z += s1.x * f.z;
        acc.w += s1.y * f.w;
    }

    const float4 bl = *reinterpret_cast<const float4*>(&bias[off]);
    float4 o;
    o.x = tanhf(acc.x) + bl.x;
    o.y = tanhf(acc.y) + bl.y;
    o.z = tanhf(acc.z) + bl.z;
    o.w = tanhf(acc.w) + bl.w;
    __stcs(reinterpret_cast<float4*>(&out[(size_t)n * NN_D + off]), o);
}

// ---------------------------------------------------------------------------
// Launch
// ---------------------------------------------------------------------------
extern "C" void kernel_launch(void* const* d_in, const int* in_sizes, int n_in,
                              void* d_out, int out_size)
{
    const float* x    = (const float*)d_in[0];
    const float* fe   = (const float*)d_in[1];
    const int*   a2a  = (const int*)d_in[2];
    const int*   n2e  = (const int*)d_in[3];
    const float* W    = (const float*)d_in[4];
    const float* blin = (const float*)d_in[5];
    const float* bias = (const float*)d_in[6];
    float*       out  = (float*)d_out;

    const int M = in_sizes[0] / NN_D;               // 50000

    __half* sup = nullptr;
    cudaGetSymbolAddress((void**)&sup, g_support_h);

    cudaFuncSetAttribute(gemm_mma_kernel,
                         cudaFuncAttributeMaxDynamicSharedMemorySize, SMEM_GEMM);

    dim3 ggrid((M + BM - 1) / BM, NN_D / BN);       // (391, 4)
    gemm_mma_kernel<<<ggrid, 256, SMEM_GEMM>>>(x, W, blin, sup, M);

    agg_kernel<<<M, 64>>>(sup, fe, a2a, n2e, bias, out, M);
}